// round 9
// baseline (speedup 1.0000x reference)
#include <cuda_runtime.h>

// DropBlock, 2 kernels + PDL overlap:
//   mask_kernel (64 thr): bit-parallel separable 7x7 backward dilation of
//     (u < GAMMA); writes mask*scale to g_ms4; triggers PDL completion.
//   apply_kernel (PDL secondary): prefetches 4 float4s of x with __ldcg
//     (L2-resident across graph replays: x=98MB < 126MB L2, while __stcs
//     out stores stay evict-first) before cudaGridDependencySynchronize().
// GAMMA = 0.1/49 * (56^2/50^2) = 0.00256 exactly.

#define H 56
#define W 56
#define HW 3136          // 56*56
#define HW4 784          // HW/4
#define GAMMA 0.00256f
#define THREADS 256
#define V4_PER_THREAD 4
#define V4_PER_CTA (THREADS * V4_PER_THREAD)   // 1024

// mask * scale, packed for float4 loads (12.5 KB, L2 resident)
__device__ float4 g_ms4[HW4];

__global__ void __launch_bounds__(64) mask_kernel(const float4* __restrict__ u4) {
    __shared__ unsigned long long rowd[H];
    __shared__ int pc[H];
    const int tid = threadIdx.x;

    unsigned long long dil = 0ULL;

    // ── row phase: load own row (14 aligned float4), threshold, dilate ──
    if (tid < H) {
        float4 r[14];
        #pragma unroll
        for (int j = 0; j < 14; ++j) r[j] = __ldg(&u4[tid * 14 + j]);
        unsigned long long s = 0ULL;
        #pragma unroll
        for (int j = 0; j < 14; ++j) {
            const int w = j * 4;
            s |= (unsigned long long)(r[j].x < GAMMA) << (w + 0);
            s |= (unsigned long long)(r[j].y < GAMMA) << (w + 1);
            s |= (unsigned long long)(r[j].z < GAMMA) << (w + 2);
            s |= (unsigned long long)(r[j].w < GAMMA) << (w + 3);
        }
        unsigned long long a = s | (s << 1);     // shifts {0,1}
        unsigned long long b = a | (a << 2);     // shifts {0..3}
        unsigned long long c = b | (b << 3);     // shifts {0..6}
        rowd[tid] = c & ((1ULL << W) - 1ULL);
    }
    __syncthreads();

    // ── column phase: rolling OR over rows h-6..h, popcount ──
    if (tid < H) {
        const int h0 = tid - 6 < 0 ? 0 : tid - 6;
        unsigned long long d = 0ULL;
        for (int h = h0; h <= tid; ++h) d |= rowd[h];
        dil = d;
        pc[tid] = __popcll(d);
    }
    __syncthreads();

    // ── scale (redundant per-thread sum) + float4 mask writes ──
    if (tid < H) {
        int tot = 0;
        #pragma unroll
        for (int h = 0; h < H; ++h) tot += pc[h];
        const float scale = (float)HW / (float)(HW - tot);
        #pragma unroll
        for (int j = 0; j < 14; ++j) {
            const unsigned long long bits = dil >> (j * 4);
            float4 mk;
            mk.x = (bits & 1ULL) ? 0.0f : scale;
            mk.y = (bits & 2ULL) ? 0.0f : scale;
            mk.z = (bits & 4ULL) ? 0.0f : scale;
            mk.w = (bits & 8ULL) ? 0.0f : scale;
            g_ms4[tid * 14 + j] = mk;
        }
    }
    __threadfence();
    cudaTriggerProgrammaticLaunchCompletion();
}

__global__ void __launch_bounds__(THREADS) apply_kernel(
    const float4* __restrict__ x, float4* __restrict__ out) {
    const int base = blockIdx.x * V4_PER_CTA + threadIdx.x;

    // front-batch all 4 x loads before depending on mask_kernel.
    // __ldcg: keep x in L2 (resident across graph replays), skip L1.
    float4 v[V4_PER_THREAD];
    #pragma unroll
    for (int k = 0; k < V4_PER_THREAD; ++k)
        v[k] = __ldcg(&x[base + k * THREADS]);

    cudaGridDependencySynchronize();

    int s4 = base % HW4;                         // incremental wrap
    #pragma unroll
    for (int k = 0; k < V4_PER_THREAD; ++k) {
        const float4 mk = g_ms4[s4];
        v[k].x *= mk.x; v[k].y *= mk.y; v[k].z *= mk.z; v[k].w *= mk.w;
        __stcs(&out[base + k * THREADS], v[k]);  // evict-first write stream
        s4 += THREADS;
        if (s4 >= HW4) s4 -= HW4;
    }
}

extern "C" void kernel_launch(void* const* d_in, const int* in_sizes, int n_in,
                              void* d_out, int out_size) {
    const float* x = (const float*)d_in[0];   // (32,256,56,56) f32
    const float* u = (const float*)d_in[1];   // (56,56) f32

    mask_kernel<<<1, 64>>>((const float4*)u);

    // 6,422,528 float4 = 6272 CTAs * 256 thr * 4
    const int n4 = out_size / 4;

    cudaLaunchConfig_t cfg = {};
    cfg.gridDim = dim3(n4 / V4_PER_CTA, 1, 1);
    cfg.blockDim = dim3(THREADS, 1, 1);
    cfg.dynamicSmemBytes = 0;
    cfg.stream = 0;
    cudaLaunchAttribute attr[1];
    attr[0].id = cudaLaunchAttributeProgrammaticStreamSerialization;
    attr[0].val.programmaticStreamSerializationAllowed = 1;
    cfg.attrs = attr;
    cfg.numAttrs = 1;
    cudaLaunchKernelEx(&cfg, apply_kernel, (const float4*)x, (float4*)d_out);
}

// round 10
// speedup vs baseline: 1.0192x; 1.0192x over previous
#include <cuda_runtime.h>

// DropBlock, 2 kernels + PDL overlap:
//   mask_kernel (64 thr): bit-parallel separable 7x7 backward dilation of
//     (u < GAMMA); writes mask*scale to g_ms4; triggers PDL completion.
//   apply_kernel (PDL secondary, V4=2 best-measured geometry): prefetches
//     2 float4s of x with __ldcs before cudaGridDependencySynchronize().
// GAMMA = 0.1/49 * (56^2/50^2) = 0.00256 exactly.
// R9 lesson: __ldcg regressed (no useful cross-replay L2 residency);
// evict-first (__ldcs/__stcs) on both streams is the right policy.

#define H 56
#define W 56
#define HW 3136          // 56*56
#define HW4 784          // HW/4
#define GAMMA 0.00256f
#define THREADS 256
#define V4_PER_THREAD 2
#define V4_PER_CTA (THREADS * V4_PER_THREAD)   // 512

// mask * scale, packed for float4 loads (12.5 KB, L2 resident)
__device__ float4 g_ms4[HW4];

__global__ void __launch_bounds__(64) mask_kernel(const float4* __restrict__ u4) {
    __shared__ unsigned long long rowd[H];
    __shared__ int pc[H];
    const int tid = threadIdx.x;

    unsigned long long dil = 0ULL;

    // ── row phase: load own row (14 aligned float4), threshold, dilate ──
    if (tid < H) {
        float4 r[14];
        #pragma unroll
        for (int j = 0; j < 14; ++j) r[j] = __ldg(&u4[tid * 14 + j]);
        unsigned long long s = 0ULL;
        #pragma unroll
        for (int j = 0; j < 14; ++j) {
            const int w = j * 4;
            s |= (unsigned long long)(r[j].x < GAMMA) << (w + 0);
            s |= (unsigned long long)(r[j].y < GAMMA) << (w + 1);
            s |= (unsigned long long)(r[j].z < GAMMA) << (w + 2);
            s |= (unsigned long long)(r[j].w < GAMMA) << (w + 3);
        }
        unsigned long long a = s | (s << 1);     // shifts {0,1}
        unsigned long long b = a | (a << 2);     // shifts {0..3}
        unsigned long long c = b | (b << 3);     // shifts {0..6}
        rowd[tid] = c & ((1ULL << W) - 1ULL);
    }
    __syncthreads();

    // ── column phase: rolling OR over rows h-6..h, popcount ──
    if (tid < H) {
        const int h0 = tid - 6 < 0 ? 0 : tid - 6;
        unsigned long long d = 0ULL;
        for (int h = h0; h <= tid; ++h) d |= rowd[h];
        dil = d;
        pc[tid] = __popcll(d);
    }
    __syncthreads();

    // ── scale (redundant per-thread sum) + float4 mask writes ──
    if (tid < H) {
        int tot = 0;
        #pragma unroll
        for (int h = 0; h < H; ++h) tot += pc[h];
        const float scale = (float)HW / (float)(HW - tot);
        #pragma unroll
        for (int j = 0; j < 14; ++j) {
            const unsigned long long bits = dil >> (j * 4);
            float4 mk;
            mk.x = (bits & 1ULL) ? 0.0f : scale;
            mk.y = (bits & 2ULL) ? 0.0f : scale;
            mk.z = (bits & 4ULL) ? 0.0f : scale;
            mk.w = (bits & 8ULL) ? 0.0f : scale;
            g_ms4[tid * 14 + j] = mk;
        }
    }
    __threadfence();
    cudaTriggerProgrammaticLaunchCompletion();
}

__global__ void __launch_bounds__(THREADS) apply_kernel(
    const float4* __restrict__ x, float4* __restrict__ out) {
    const int base = blockIdx.x * V4_PER_CTA + threadIdx.x;

    // front-batch both x loads before depending on mask_kernel
    float4 v0 = __ldcs(&x[base]);
    float4 v1 = __ldcs(&x[base + THREADS]);

    cudaGridDependencySynchronize();

    int s4 = base % HW4;
    const float4 m0 = g_ms4[s4];
    s4 += THREADS;
    if (s4 >= HW4) s4 -= HW4;
    const float4 m1 = g_ms4[s4];

    v0.x *= m0.x; v0.y *= m0.y; v0.z *= m0.z; v0.w *= m0.w;
    v1.x *= m1.x; v1.y *= m1.y; v1.z *= m1.z; v1.w *= m1.w;
    __stcs(&out[base], v0);
    __stcs(&out[base + THREADS], v1);
}

extern "C" void kernel_launch(void* const* d_in, const int* in_sizes, int n_in,
                              void* d_out, int out_size) {
    const float* x = (const float*)d_in[0];   // (32,256,56,56) f32
    const float* u = (const float*)d_in[1];   // (56,56) f32

    mask_kernel<<<1, 64>>>((const float4*)u);

    // 6,422,528 float4 = 12544 CTAs * 256 thr * 2
    const int n4 = out_size / 4;

    cudaLaunchConfig_t cfg = {};
    cfg.gridDim = dim3(n4 / V4_PER_CTA, 1, 1);
    cfg.blockDim = dim3(THREADS, 1, 1);
    cfg.dynamicSmemBytes = 0;
    cfg.stream = 0;
    cudaLaunchAttribute attr[1];
    attr[0].id = cudaLaunchAttributeProgrammaticStreamSerialization;
    attr[0].val.programmaticStreamSerializationAllowed = 1;
    cfg.attrs = attr;
    cfg.numAttrs = 1;
    cudaLaunchKernelEx(&cfg, apply_kernel, (const float4*)x, (float4*)d_out);
}

// round 11
// speedup vs baseline: 1.1174x; 1.0963x over previous
#include <cuda_runtime.h>

// DropBlock, single fused kernel with FRONT-BATCHED stream loads:
//   1. issue all 8 x float4 loads (fills DRAM pipe from cycle ~1; LDGs stay
//      ahead of barriers in SASS — BAR.SYNC drains STS, not LDG)
//   2. stage u to shared, bit-parallel separable 7x7 backward dilation,
//      materialize mask*scale as float4[784] in shared (reusing u's buffer)
//   3. consume x loads, multiply, streaming-store
// R4's fused failure had loads AFTER the mask barriers (exposure = sum);
// front-batching makes exposure = max(prologue, load latency) and removes
// the ~3us PDL gap of the 2-kernel versions.
// GAMMA = 0.1/49 * (56^2/50^2) = 0.00256 exactly.

#define H 56
#define W 56
#define HW 3136          // 56*56
#define HW4 784          // HW/4
#define GAMMA 0.00256f
#define THREADS 256
#define V4 8
#define V4_PER_CTA (THREADS * V4)   // 2048

__global__ void __launch_bounds__(THREADS) dropblock_fused(
    const float4* __restrict__ x, const float4* __restrict__ u4,
    float4* __restrict__ out) {
    // 12.5KB buffer reused: u floats (phase 2-3) then mask float4s (phase 5-6)
    __shared__ __align__(16) float s_buf[HW];
    __shared__ unsigned long long rowd[H];
    __shared__ unsigned long long dil[H];
    __shared__ int pc[H];

    const int tid = threadIdx.x;
    const int base = blockIdx.x * V4_PER_CTA + tid;

    // ── 1. front-batch ALL stream loads (MLP=8, before any barrier) ──
    float4 v[V4];
    #pragma unroll
    for (int k = 0; k < V4; ++k)
        v[k] = __ldcs(&x[base + k * THREADS]);

    // ── 2. stage u into shared (784 float4 over 256 threads, coalesced) ──
    float4* s_buf4 = reinterpret_cast<float4*>(s_buf);
    #pragma unroll
    for (int j = 0; j < 4; ++j) {
        const int i = tid + j * THREADS;
        if (i < HW4) s_buf4[i] = __ldg(&u4[i]);
    }
    __syncthreads();

    // ── 3. row-wise backward dilation (width 7) as bit ops ──
    if (tid < H) {
        unsigned long long s = 0ULL;
        #pragma unroll
        for (int w = 0; w < W; ++w)
            s |= (unsigned long long)(s_buf[tid * W + w] < GAMMA) << w;
        unsigned long long a = s | (s << 1);     // shifts {0,1}
        unsigned long long b = a | (a << 2);     // shifts {0..3}
        unsigned long long c = b | (b << 3);     // shifts {0..6}
        rowd[tid] = c & ((1ULL << W) - 1ULL);
    }
    __syncthreads();

    // ── 4. column-wise rolling OR over rows h-6..h + popcount ──
    if (tid < H) {
        const int h0 = tid - 6 < 0 ? 0 : tid - 6;
        unsigned long long d = 0ULL;
        for (int h = h0; h <= tid; ++h) d |= rowd[h];
        dil[tid] = d;
        pc[tid] = __popcll(d);
    }
    __syncthreads();

    // ── 5. scale (redundant per-thread sum of 56 ints) + mask float4s
    //       written over u's dead shared buffer ──
    int tot = 0;
    #pragma unroll
    for (int h = 0; h < H; ++h) tot += pc[h];
    const float scale = (float)HW / (float)(HW - tot);
    #pragma unroll
    for (int j = 0; j < 4; ++j) {
        const int s4 = tid + j * THREADS;
        if (s4 < HW4) {
            const int h = s4 / 14;               // 14 float4 per row
            const int w0 = (s4 % 14) * 4;
            const unsigned long long bits = dil[h] >> w0;
            float4 mk;
            mk.x = (bits & 1ULL) ? 0.0f : scale;
            mk.y = (bits & 2ULL) ? 0.0f : scale;
            mk.z = (bits & 4ULL) ? 0.0f : scale;
            mk.w = (bits & 8ULL) ? 0.0f : scale;
            s_buf4[s4] = mk;
        }
    }
    __syncthreads();

    // ── 6. consume the front-batched loads, multiply, streaming-store ──
    int s4 = base % HW4;                         // incremental wrap
    #pragma unroll
    for (int k = 0; k < V4; ++k) {
        const float4 mk = s_buf4[s4];
        v[k].x *= mk.x; v[k].y *= mk.y; v[k].z *= mk.z; v[k].w *= mk.w;
        __stcs(&out[base + k * THREADS], v[k]);
        s4 += THREADS;
        if (s4 >= HW4) s4 -= HW4;
    }
}

extern "C" void kernel_launch(void* const* d_in, const int* in_sizes, int n_in,
                              void* d_out, int out_size) {
    const float* x = (const float*)d_in[0];   // (32,256,56,56) f32
    const float* u = (const float*)d_in[1];   // (56,56) f32

    // 6,422,528 float4 = 3136 CTAs * 256 thr * 8
    const int n4 = out_size / 4;
    dropblock_fused<<<n4 / V4_PER_CTA, THREADS>>>(
        (const float4*)x, (const float4*)u, (float4*)d_out);
}